// round 16
// baseline (speedup 1.0000x reference)
#include <cuda_runtime.h>
#include <cstdint>

#define NT1      256
#define MTILE    64
#define NCHUNKS  16
#define NH       64
#define NB       64
#define DIMC     1024

// stage: A_hi 8K + A_lo 8K + B hi/lo 16K = 32 KB, two stages
#define STAGE_BYTES 32768
#define OFF_AHI  0
#define OFF_ALO  8192
#define OFF_BHI  16384
// post-GEMM overlay
#define OFF_ZS   0              // float[64*66] = 16896 B
#define SMEM_TOTAL (2 * STAGE_BYTES)

#define TBLN     4096           // grid points over [-8, 8), step 1/256
#define TSCALE   256.0f
#define TOFF     2048.0f

__device__ float4 g_q[NH * NB];            // {s, -2sc', sc'^2, ow} (bias folded)
__device__ float2 g_tbl[NH * TBLN];        // per-h score table {f_i, f_{i+1}}
__device__ __align__(16) unsigned char g_wt[NCHUNKS * 16384];  // pre-split W tiles

static __device__ __forceinline__ uint32_t smem_u32(const void* p) {
    uint32_t a;
    asm("{ .reg .u64 t; cvta.to.shared.u64 t, %1; cvt.u32.u64 %0, t; }" : "=r"(a) : "l"(p));
    return a;
}

#define CP_ASYNC16(dst, src) \
    asm volatile("cp.async.ca.shared.global [%0], [%1], 16;" :: "r"(dst), "l"(src) : "memory")
#define CP_COMMIT() asm volatile("cp.async.commit_group;" ::: "memory")
#define CP_WAIT0()  asm volatile("cp.async.wait_group 0;" ::: "memory")

static __device__ __forceinline__ void split_pack(float4 v, uint32_t& hi01, uint32_t& hi23,
                                                  uint32_t& lo01, uint32_t& lo23) {
    uint32_t u0 = __float_as_uint(v.x), u1 = __float_as_uint(v.y);
    uint32_t u2 = __float_as_uint(v.z), u3 = __float_as_uint(v.w);
    hi01 = __byte_perm(u0, u1, 0x7632);
    hi23 = __byte_perm(u2, u3, 0x7632);
    float l0 = v.x - __uint_as_float(u0 & 0xffff0000u);
    float l1 = v.y - __uint_as_float(u1 & 0xffff0000u);
    float l2 = v.z - __uint_as_float(u2 & 0xffff0000u);
    float l3 = v.w - __uint_as_float(u3 & 0xffff0000u);
    asm("cvt.rn.bf16x2.f32 %0, %1, %2;" : "=r"(lo01) : "f"(l1), "f"(l0));
    asm("cvt.rn.bf16x2.f32 %0, %1, %2;" : "=r"(lo23) : "f"(l3), "f"(l2));
}

static __device__ __forceinline__ void split_store(float4 v, uint32_t ahi, uint32_t alo) {
    uint32_t hi01, hi23, lo01, lo23;
    split_pack(v, hi01, hi23, lo01, lo23);
    asm volatile("st.shared.v2.b32 [%0], {%1,%2};" :: "r"(ahi), "r"(hi01), "r"(hi23) : "memory");
    asm volatile("st.shared.v2.b32 [%0], {%1,%2};" :: "r"(alo), "r"(lo01), "r"(lo23) : "memory");
}

#define LDSM4(r0, r1, r2, r3, a) \
    asm volatile("ldmatrix.sync.aligned.m8n8.x4.shared.b16 {%0,%1,%2,%3}, [%4];" \
                 : "=r"(r0), "=r"(r1), "=r"(r2), "=r"(r3) : "r"(a))

#define MMA(c, a0, a1, a2, a3, b0, b1) \
    asm volatile("mma.sync.aligned.m16n8k16.row.col.f32.bf16.bf16.f32 " \
                 "{%0,%1,%2,%3}, {%4,%5,%6,%7}, {%8,%9}, {%0,%1,%2,%3};" \
                 : "+f"((c)[0]), "+f"((c)[1]), "+f"((c)[2]), "+f"((c)[3]) \
                 : "r"(a0), "r"(a1), "r"(a2), "r"(a3), "r"(b0), "r"(b1))

// ---- table point evaluator ----
static __device__ __forceinline__ void tbl_store(int h, int i, const float4* qs) {
    if (i > TBLN) return;
    float z = (float)i * (1.0f / TSCALE) - 8.0f;
    float f = 0.f;
#pragma unroll 8
    for (int k = 0; k < NB; ++k) {
        float4 q = qs[k];
        float pp = fmaf(fmaf(q.x, z, q.y), z, q.z);
        float e;
        asm("ex2.approx.f32 %0, %1;" : "=f"(e) : "f"(pp));
        f = fmaf(e, q.w, f);
    }
    float* tb = (float*)(g_tbl + h * TBLN);
    if (i < TBLN) tb[2 * i] = f;
    if (i > 0)    tb[2 * i - 1] = f;
}

// ---- single prep kernel: blocks 0-63 W split; blocks 64-575 coeffs + table ----
__global__ void rbf_prep(const float* __restrict__ in_b,
                         const float* __restrict__ centers,
                         const float* __restrict__ log_widths,
                         const float* __restrict__ out_weight,
                         const float* __restrict__ in_w)
{
    __shared__ float4 qs[NB];
    const int bid = blockIdx.x;
    const int tid = threadIdx.x;

    if (bid < 64) {
        int t = bid * 256 + tid;          // 0..16383
        int row = t >> 8;                 // h
        int c4g = t & 255;
        int ch  = c4g >> 4;
        int c4  = c4g & 15;
        float4 v = ((const float4*)in_w)[row * 256 + c4g];
        uint32_t hi01, hi23, lo01, lo23;
        split_pack(v, hi01, hi23, lo01, lo23);
        uint32_t sw = ((uint32_t)row * 128u + (uint32_t)c4 * 8u) ^ ((uint32_t)(row & 7) << 4);
        unsigned char* base = g_wt + ch * 16384;
        *(uint2*)(base + sw)        = make_uint2(hi01, hi23);
        *(uint2*)(base + 8192 + sw) = make_uint2(lo01, lo23);
        return;
    }

    const int t   = bid - 64;             // 0..511
    const int h   = t >> 3;
    const int seg = t & 7;

    if (tid < NB) {
        int i = h * NB + tid;
        float lw = log_widths[i];
        float sp = (lw > 15.f) ? lw : log1pf(expf(lw));
        float w = sp + 0.001f;
        float s = -1.4426950408889634f / (w * w);
        float c = centers[i] - in_b[h];
        float4 q;
        q.x = s; q.y = -2.f * s * c; q.z = s * c * c; q.w = out_weight[i];
        qs[tid] = q;
        if (seg == 0) g_q[i] = q;
    }
    __syncthreads();

    int i0 = seg * 512 + tid;
    tbl_store(h, i0, qs);
    tbl_store(h, i0 + 256, qs);
    if (seg == 7 && tid == 0) tbl_store(h, TBLN, qs);
}

// ---- fused GEMM + table-lookup RBF: MTILE=64, 3 CTAs/SM ----
__global__ void __launch_bounds__(NT1, 3)
rbf_fused_kernel(const float* __restrict__ x,
                 const float* __restrict__ out_bias,
                 float* __restrict__ out)
{
    extern __shared__ char smem[];
    const uint32_t sb = smem_u32(smem);
    const int tid = threadIdx.x;
    const int wid = tid >> 5;
    const int l   = tid & 31;
    const int wq  = wid & 1;              // token half (32 tok)
    const int wh  = wid >> 1;             // h quarter (16 h)
    const int tok0 = blockIdx.x * MTILE;

    // acc[m][nt][4]: m = 16-token half, nt = n8 tile within 16 h
    float acc[2][2][4];
#pragma unroll
    for (int m = 0; m < 2; ++m)
#pragma unroll
        for (int nt = 0; nt < 2; ++nt)
#pragma unroll
            for (int j = 0; j < 4; ++j) acc[m][nt][j] = 0.f;

    // producer: r0 = row (0..63), c4 base (0..3), 4 batches stride 4
    const int r0  = tid >> 2;
    const int c4b = tid & 3;
    const float4* xg = (const float4*)x;

    const uint32_t key  = (uint32_t)(l & 7);
    const uint32_t rowA = (uint32_t)(wq * 32 + (l & 15));
    const uint32_t chA  = (uint32_t)((l >> 4) & 1);
    const uint32_t rowB = (uint32_t)(wh * 16 + ((l >> 4) << 3) + (l & 7));
    const uint32_t chB  = (uint32_t)((l >> 3) & 1);

    float4 pa[4];

    // ---- prologue: chunk 0 ----
    {
        const unsigned char* src = g_wt + (uint32_t)tid * 16u;
#pragma unroll
        for (int i = 0; i < 4; ++i)
            CP_ASYNC16(sb + OFF_BHI + (uint32_t)tid * 16u + i * 4096u, src + i * 4096);
        CP_COMMIT();
#pragma unroll
        for (int b = 0; b < 4; ++b)
            pa[b] = xg[(long)(tok0 + r0) * 256 + c4b + 4 * b];
#pragma unroll
        for (int b = 0; b < 4; ++b) {
            uint32_t sw = ((uint32_t)r0 * 128u + (uint32_t)(c4b + 4 * b) * 8u)
                          ^ ((uint32_t)(r0 & 7) << 4);
            split_store(pa[b], sb + OFF_AHI + sw, sb + OFF_ALO + sw);
        }
        CP_WAIT0();
        __syncthreads();
    }

#pragma unroll 1
    for (int ch = 0; ch < NCHUNKS; ++ch) {
        const uint32_t sbase = sb + (uint32_t)(ch & 1) * STAGE_BYTES;
        const uint32_t dbase = sb + (uint32_t)((ch + 1) & 1) * STAGE_BYTES;

        if (ch < NCHUNKS - 1) {
#pragma unroll
            for (int b = 0; b < 4; ++b)
                pa[b] = xg[(long)(tok0 + r0) * 256 + (ch + 1) * 16 + c4b + 4 * b];
            const unsigned char* src = g_wt + (uint32_t)(ch + 1) * 16384u + (uint32_t)tid * 16u;
#pragma unroll
            for (int i = 0; i < 4; ++i)
                CP_ASYNC16(dbase + OFF_BHI + (uint32_t)tid * 16u + i * 4096u, src + i * 4096);
            CP_COMMIT();
        }

#pragma unroll
        for (int s = 0; s < 4; ++s) {
            const uint32_t colA = ((uint32_t)(s * 2) + chA) ^ key;
            const uint32_t colB = ((uint32_t)(s * 2) + chB) ^ key;
            uint32_t ah[2][4], al[2][4];
#pragma unroll
            for (int m = 0; m < 2; ++m) {
                uint32_t ra = (rowA + m * 16) * 128u + (colA << 4);
                LDSM4(ah[m][0], ah[m][1], ah[m][2], ah[m][3], sbase + OFF_AHI + ra);
                LDSM4(al[m][0], al[m][1], al[m][2], al[m][3], sbase + OFF_ALO + ra);
            }
            {
                uint32_t rb = rowB * 128u + (colB << 4);
                uint32_t bh[4], bl[4];
                LDSM4(bh[0], bh[1], bh[2], bh[3], sbase + OFF_BHI + rb);
                LDSM4(bl[0], bl[1], bl[2], bl[3], sbase + OFF_BHI + 8192u + rb);
#pragma unroll
                for (int m = 0; m < 2; ++m) {
                    MMA(acc[m][0], ah[m][0], ah[m][1], ah[m][2], ah[m][3], bh[0], bh[1]);
                    MMA(acc[m][1], ah[m][0], ah[m][1], ah[m][2], ah[m][3], bh[2], bh[3]);
                    MMA(acc[m][0], ah[m][0], ah[m][1], ah[m][2], ah[m][3], bl[0], bl[1]);
                    MMA(acc[m][1], ah[m][0], ah[m][1], ah[m][2], ah[m][3], bl[2], bl[3]);
                    MMA(acc[m][0], al[m][0], al[m][1], al[m][2], al[m][3], bh[0], bh[1]);
                    MMA(acc[m][1], al[m][0], al[m][1], al[m][2], al[m][3], bh[2], bh[3]);
                }
            }
            if (ch < NCHUNKS - 1 && s == 3) {
#pragma unroll
                for (int b = 0; b < 4; ++b) {
                    uint32_t sw = ((uint32_t)r0 * 128u + (uint32_t)(c4b + 4 * b) * 8u)
                                  ^ ((uint32_t)(r0 & 7) << 4);
                    split_store(pa[b], dbase + OFF_AHI + sw, dbase + OFF_ALO + sw);
                }
            }
        }
        if (ch < NCHUNKS - 1) CP_WAIT0();
        __syncthreads();
    }

    // ---- overlay: z -> smem [64][66] ----
    {
        float* zs = (float*)(smem + OFF_ZS);
        const int g = l >> 2, t = l & 3;
#pragma unroll
        for (int m = 0; m < 2; ++m)
#pragma unroll
            for (int nt = 0; nt < 2; ++nt) {
                int tok = wq * 32 + m * 16 + g;
                int hcol = wh * 16 + nt * 8 + 2 * t;
                *(float2*)(zs + tok * 66 + hcol)       = make_float2(acc[m][nt][0], acc[m][nt][1]);
                *(float2*)(zs + (tok + 8) * 66 + hcol) = make_float2(acc[m][nt][2], acc[m][nt][3]);
            }
    }
    __syncthreads();

    // ---- epilogue: table lookup; thread = quarter token (16 h) ----
    const int hq  = tid & 3;
    const int tok = tid >> 2;
    const float* zrow = (const float*)(smem + OFF_ZS) + tok * 66 + hq * 16;
    const float2* tb = g_tbl + (hq * 16) * TBLN;
    float sum = 0.f;
#pragma unroll 8
    for (int j = 0; j < 16; ++j) {
        float z = zrow[j];
        float t = fmaf(z, TSCALE, TOFF);
        int i = (int)t;
        if ((unsigned)i < (unsigned)TBLN) {
            float frac = t - (float)i;
            float2 e = __ldg(tb + j * TBLN + i);
            sum += e.x;
            sum = fmaf(frac, e.y - e.x, sum);
        } else {
            const float4* qh = g_q + (hq * 16 + j) * NB;
            float s2 = 0.f;
            for (int k = 0; k < NB; ++k) {
                float4 q = qh[k];
                float pp = fmaf(fmaf(q.x, z, q.y), z, q.z);
                float e;
                asm("ex2.approx.f32 %0, %1;" : "=f"(e) : "f"(pp));
                s2 = fmaf(e, q.w, s2);
            }
            sum += s2;
        }
    }
    sum += __shfl_xor_sync(0xffffffffu, sum, 1);
    sum += __shfl_xor_sync(0xffffffffu, sum, 2);
    if (hq == 0) out[tok0 + tok] = sum + __ldg(out_bias);
}

extern "C" void kernel_launch(void* const* d_in, const int* in_sizes, int n_in,
                              void* d_out, int out_size)
{
    const float* x          = (const float*)d_in[0];
    const float* in_w       = (const float*)d_in[1];
    const float* in_b       = (const float*)d_in[2];
    const float* centers    = (const float*)d_in[3];
    const float* log_widths = (const float*)d_in[4];
    const float* out_weight = (const float*)d_in[5];
    const float* out_bias   = (const float*)d_in[6];
    float* out = (float*)d_out;

    int ntok = in_sizes[0] / DIMC;          // 65536

    rbf_prep<<<576, 256>>>(in_b, centers, log_widths, out_weight, in_w);

    cudaFuncSetAttribute(rbf_fused_kernel,
                         cudaFuncAttributeMaxDynamicSharedMemorySize, SMEM_TOTAL);
    rbf_fused_kernel<<<ntok / MTILE, NT1, SMEM_TOTAL>>>(x, out_bias, out);
}

// round 17
// speedup vs baseline: 1.0106x; 1.0106x over previous
#include <cuda_runtime.h>
#include <cstdint>

#define NT1      256
#define MTILE    64
#define NCHUNKS  16
#define NH       64
#define NB       64
#define DIMC     1024

// stage: A_hi 8K + A_lo 8K + B hi/lo 16K = 32 KB, two stages
#define STAGE_BYTES 32768
#define OFF_AHI  0
#define OFF_ALO  8192
#define OFF_BHI  16384
// post-GEMM overlay
#define OFF_ZS   0              // float[64*66] = 16896 B
#define SMEM_TOTAL (2 * STAGE_BYTES)

#define TBLN     4096           // grid points over [-8, 8), step 1/256
#define TSCALE   256.0f
#define TOFF     2048.0f

__device__ float4 g_q[NH * NB];            // {s, -2sc', sc'^2, ow} (bias folded)
__device__ float2 g_tbl[NH * TBLN];        // per-h score table {f_i, f_{i+1}}
__device__ __align__(16) unsigned char g_wt[NCHUNKS * 16384];  // pre-split W tiles

static __device__ __forceinline__ uint32_t smem_u32(const void* p) {
    uint32_t a;
    asm("{ .reg .u64 t; cvta.to.shared.u64 t, %1; cvt.u32.u64 %0, t; }" : "=r"(a) : "l"(p));
    return a;
}

#define CP_ASYNC16(dst, src) \
    asm volatile("cp.async.ca.shared.global [%0], [%1], 16;" :: "r"(dst), "l"(src) : "memory")
#define CP_COMMIT() asm volatile("cp.async.commit_group;" ::: "memory")
#define CP_WAIT0()  asm volatile("cp.async.wait_group 0;" ::: "memory")

static __device__ __forceinline__ void split_pack(float4 v, uint32_t& hi01, uint32_t& hi23,
                                                  uint32_t& lo01, uint32_t& lo23) {
    uint32_t u0 = __float_as_uint(v.x), u1 = __float_as_uint(v.y);
    uint32_t u2 = __float_as_uint(v.z), u3 = __float_as_uint(v.w);
    hi01 = __byte_perm(u0, u1, 0x7632);
    hi23 = __byte_perm(u2, u3, 0x7632);
    float l0 = v.x - __uint_as_float(u0 & 0xffff0000u);
    float l1 = v.y - __uint_as_float(u1 & 0xffff0000u);
    float l2 = v.z - __uint_as_float(u2 & 0xffff0000u);
    float l3 = v.w - __uint_as_float(u3 & 0xffff0000u);
    asm("cvt.rn.bf16x2.f32 %0, %1, %2;" : "=r"(lo01) : "f"(l1), "f"(l0));
    asm("cvt.rn.bf16x2.f32 %0, %1, %2;" : "=r"(lo23) : "f"(l3), "f"(l2));
}

static __device__ __forceinline__ void split_store(float4 v, uint32_t ahi, uint32_t alo) {
    uint32_t hi01, hi23, lo01, lo23;
    split_pack(v, hi01, hi23, lo01, lo23);
    asm volatile("st.shared.v2.b32 [%0], {%1,%2};" :: "r"(ahi), "r"(hi01), "r"(hi23) : "memory");
    asm volatile("st.shared.v2.b32 [%0], {%1,%2};" :: "r"(alo), "r"(lo01), "r"(lo23) : "memory");
}

#define LDSM4(r0, r1, r2, r3, a) \
    asm volatile("ldmatrix.sync.aligned.m8n8.x4.shared.b16 {%0,%1,%2,%3}, [%4];" \
                 : "=r"(r0), "=r"(r1), "=r"(r2), "=r"(r3) : "r"(a))

#define MMA(c, a0, a1, a2, a3, b0, b1) \
    asm volatile("mma.sync.aligned.m16n8k16.row.col.f32.bf16.bf16.f32 " \
                 "{%0,%1,%2,%3}, {%4,%5,%6,%7}, {%8,%9}, {%0,%1,%2,%3};" \
                 : "+f"((c)[0]), "+f"((c)[1]), "+f"((c)[2]), "+f"((c)[3]) \
                 : "r"(a0), "r"(a1), "r"(a2), "r"(a3), "r"(b0), "r"(b1))

// ---- table point evaluator ----
static __device__ __forceinline__ void tbl_store(int h, int i, const float4* qs) {
    if (i > TBLN) return;
    float z = (float)i * (1.0f / TSCALE) - 8.0f;
    float f = 0.f;
#pragma unroll 8
    for (int k = 0; k < NB; ++k) {
        float4 q = qs[k];
        float pp = fmaf(fmaf(q.x, z, q.y), z, q.z);
        float e;
        asm("ex2.approx.f32 %0, %1;" : "=f"(e) : "f"(pp));
        f = fmaf(e, q.w, f);
    }
    float* tb = (float*)(g_tbl + h * TBLN);
    if (i < TBLN) tb[2 * i] = f;
    if (i > 0)    tb[2 * i - 1] = f;
}

// ---- single prep kernel: blocks 0-63 W split; blocks 64-575 coeffs + table ----
__global__ void rbf_prep(const float* __restrict__ in_b,
                         const float* __restrict__ centers,
                         const float* __restrict__ log_widths,
                         const float* __restrict__ out_weight,
                         const float* __restrict__ in_w)
{
    __shared__ float4 qs[NB];
    const int bid = blockIdx.x;
    const int tid = threadIdx.x;

    if (bid < 64) {
        int t = bid * 256 + tid;          // 0..16383
        int row = t >> 8;                 // h
        int c4g = t & 255;
        int ch  = c4g >> 4;
        int c4  = c4g & 15;
        float4 v = ((const float4*)in_w)[row * 256 + c4g];
        uint32_t hi01, hi23, lo01, lo23;
        split_pack(v, hi01, hi23, lo01, lo23);
        uint32_t sw = ((uint32_t)row * 128u + (uint32_t)c4 * 8u) ^ ((uint32_t)(row & 7) << 4);
        unsigned char* base = g_wt + ch * 16384;
        *(uint2*)(base + sw)        = make_uint2(hi01, hi23);
        *(uint2*)(base + 8192 + sw) = make_uint2(lo01, lo23);
        return;
    }

    const int t   = bid - 64;             // 0..511
    const int h   = t >> 3;
    const int seg = t & 7;

    if (tid < NB) {
        int i = h * NB + tid;
        float lw = log_widths[i];
        float sp = (lw > 15.f) ? lw : log1pf(expf(lw));
        float w = sp + 0.001f;
        float s = -1.4426950408889634f / (w * w);
        float c = centers[i] - in_b[h];
        float4 q;
        q.x = s; q.y = -2.f * s * c; q.z = s * c * c; q.w = out_weight[i];
        qs[tid] = q;
        if (seg == 0) g_q[i] = q;
    }
    __syncthreads();

    int i0 = seg * 512 + tid;
    tbl_store(h, i0, qs);
    tbl_store(h, i0 + 256, qs);
    if (seg == 7 && tid == 0) tbl_store(h, TBLN, qs);
}

// ---- fused GEMM + table-lookup RBF: MTILE=64, 3 CTAs/SM ----
__global__ void __launch_bounds__(NT1, 3)
rbf_fused_kernel(const float* __restrict__ x,
                 const float* __restrict__ out_bias,
                 float* __restrict__ out)
{
    extern __shared__ char smem[];
    const uint32_t sb = smem_u32(smem);
    const int tid = threadIdx.x;
    const int wid = tid >> 5;
    const int l   = tid & 31;
    const int wq  = wid & 1;              // token half (32 tok)
    const int wh  = wid >> 1;             // h quarter (16 h)
    const int tok0 = blockIdx.x * MTILE;

    // acc[m][nt][4]: m = 16-token half, nt = n8 tile within 16 h
    float acc[2][2][4];
#pragma unroll
    for (int m = 0; m < 2; ++m)
#pragma unroll
        for (int nt = 0; nt < 2; ++nt)
#pragma unroll
            for (int j = 0; j < 4; ++j) acc[m][nt][j] = 0.f;

    // producer: r0 = row (0..63), c4 base (0..3), 4 batches stride 4
    const int r0  = tid >> 2;
    const int c4b = tid & 3;
    const float4* xg = (const float4*)x;

    const uint32_t key  = (uint32_t)(l & 7);
    const uint32_t rowA = (uint32_t)(wq * 32 + (l & 15));
    const uint32_t chA  = (uint32_t)((l >> 4) & 1);
    const uint32_t rowB = (uint32_t)(wh * 16 + ((l >> 4) << 3) + (l & 7));
    const uint32_t chB  = (uint32_t)((l >> 3) & 1);

    float4 pa[4];

    // ---- prologue: chunk 0 ----
    {
        const unsigned char* src = g_wt + (uint32_t)tid * 16u;
#pragma unroll
        for (int i = 0; i < 4; ++i)
            CP_ASYNC16(sb + OFF_BHI + (uint32_t)tid * 16u + i * 4096u, src + i * 4096);
        CP_COMMIT();
#pragma unroll
        for (int b = 0; b < 4; ++b)
            pa[b] = xg[(long)(tok0 + r0) * 256 + c4b + 4 * b];
#pragma unroll
        for (int b = 0; b < 4; ++b) {
            uint32_t sw = ((uint32_t)r0 * 128u + (uint32_t)(c4b + 4 * b) * 8u)
                          ^ ((uint32_t)(r0 & 7) << 4);
            split_store(pa[b], sb + OFF_AHI + sw, sb + OFF_ALO + sw);
        }
        CP_WAIT0();
        __syncthreads();
    }

#pragma unroll 1
    for (int ch = 0; ch < NCHUNKS; ++ch) {
        const uint32_t sbase = sb + (uint32_t)(ch & 1) * STAGE_BYTES;
        const uint32_t dbase = sb + (uint32_t)((ch + 1) & 1) * STAGE_BYTES;

        if (ch < NCHUNKS - 1) {
#pragma unroll
            for (int b = 0; b < 4; ++b)
                pa[b] = xg[(long)(tok0 + r0) * 256 + (ch + 1) * 16 + c4b + 4 * b];
            const unsigned char* src = g_wt + (uint32_t)(ch + 1) * 16384u + (uint32_t)tid * 16u;
#pragma unroll
            for (int i = 0; i < 4; ++i)
                CP_ASYNC16(dbase + OFF_BHI + (uint32_t)tid * 16u + i * 4096u, src + i * 4096);
            CP_COMMIT();
        }

#pragma unroll
        for (int s = 0; s < 4; ++s) {
            const uint32_t colA = ((uint32_t)(s * 2) + chA) ^ key;
            const uint32_t colB = ((uint32_t)(s * 2) + chB) ^ key;
            uint32_t ah[2][4], al[2][4];
#pragma unroll
            for (int m = 0; m < 2; ++m) {
                uint32_t ra = (rowA + m * 16) * 128u + (colA << 4);
                LDSM4(ah[m][0], ah[m][1], ah[m][2], ah[m][3], sbase + OFF_AHI + ra);
                LDSM4(al[m][0], al[m][1], al[m][2], al[m][3], sbase + OFF_ALO + ra);
            }
            {
                uint32_t rb = rowB * 128u + (colB << 4);
                uint32_t bh[4], bl[4];
                LDSM4(bh[0], bh[1], bh[2], bh[3], sbase + OFF_BHI + rb);
                LDSM4(bl[0], bl[1], bl[2], bl[3], sbase + OFF_BHI + 8192u + rb);
#pragma unroll
                for (int m = 0; m < 2; ++m) {
                    MMA(acc[m][0], ah[m][0], ah[m][1], ah[m][2], ah[m][3], bh[0], bh[1]);
                    MMA(acc[m][1], ah[m][0], ah[m][1], ah[m][2], ah[m][3], bh[2], bh[3]);
                    MMA(acc[m][0], ah[m][0], ah[m][1], ah[m][2], ah[m][3], bl[0], bl[1]);
                    MMA(acc[m][1], ah[m][0], ah[m][1], ah[m][2], ah[m][3], bl[2], bl[3]);
                    MMA(acc[m][0], al[m][0], al[m][1], al[m][2], al[m][3], bh[0], bh[1]);
                    MMA(acc[m][1], al[m][0], al[m][1], al[m][2], al[m][3], bh[2], bh[3]);
                }
            }
            if (ch < NCHUNKS - 1 && s == 3) {
#pragma unroll
                for (int b = 0; b < 4; ++b) {
                    uint32_t sw = ((uint32_t)r0 * 128u + (uint32_t)(c4b + 4 * b) * 8u)
                                  ^ ((uint32_t)(r0 & 7) << 4);
                    split_store(pa[b], dbase + OFF_AHI + sw, dbase + OFF_ALO + sw);
                }
            }
        }
        if (ch < NCHUNKS - 1) CP_WAIT0();
        __syncthreads();
    }

    // ---- overlay: z -> smem [64][66] ----
    {
        float* zs = (float*)(smem + OFF_ZS);
        const int g = l >> 2, t = l & 3;
#pragma unroll
        for (int m = 0; m < 2; ++m)
#pragma unroll
            for (int nt = 0; nt < 2; ++nt) {
                int tok = wq * 32 + m * 16 + g;
                int hcol = wh * 16 + nt * 8 + 2 * t;
                *(float2*)(zs + tok * 66 + hcol)       = make_float2(acc[m][nt][0], acc[m][nt][1]);
                *(float2*)(zs + (tok + 8) * 66 + hcol) = make_float2(acc[m][nt][2], acc[m][nt][3]);
            }
    }
    __syncthreads();

    // ---- epilogue: table lookup; thread = quarter token (16 h) ----
    const int hq  = tid & 3;
    const int tok = tid >> 2;
    const float* zrow = (const float*)(smem + OFF_ZS) + tok * 66 + hq * 16;
    const float2* tb = g_tbl + (hq * 16) * TBLN;
    float sum = 0.f;
#pragma unroll 8
    for (int j = 0; j < 16; ++j) {
        float z = zrow[j];
        float t = fmaf(z, TSCALE, TOFF);
        int i = (int)t;
        if ((unsigned)i < (unsigned)TBLN) {
            float frac = t - (float)i;
            float2 e = __ldg(tb + j * TBLN + i);
            sum += e.x;
            sum = fmaf(frac, e.y - e.x, sum);
        } else {
            const float4* qh = g_q + (hq * 16 + j) * NB;
            float s2 = 0.f;
            for (int k = 0; k < NB; ++k) {
                float4 q = qh[k];
                float pp = fmaf(fmaf(q.x, z, q.y), z, q.z);
                float e;
                asm("ex2.approx.f32 %0, %1;" : "=f"(e) : "f"(pp));
                s2 = fmaf(e, q.w, s2);
            }
            sum += s2;
        }
    }
    sum += __shfl_xor_sync(0xffffffffu, sum, 1);
    sum += __shfl_xor_sync(0xffffffffu, sum, 2);
    if (hq == 0) out[tok0 + tok] = sum + __ldg(out_bias);
}

extern "C" void kernel_launch(void* const* d_in, const int* in_sizes, int n_in,
                              void* d_out, int out_size)
{
    const float* x          = (const float*)d_in[0];
    const float* in_w       = (const float*)d_in[1];
    const float* in_b       = (const float*)d_in[2];
    const float* centers    = (const float*)d_in[3];
    const float* log_widths = (const float*)d_in[4];
    const float* out_weight = (const float*)d_in[5];
    const float* out_bias   = (const float*)d_in[6];
    float* out = (float*)d_out;

    int ntok = in_sizes[0] / DIMC;          // 65536

    rbf_prep<<<576, 256>>>(in_b, centers, log_widths, out_weight, in_w);

    cudaFuncSetAttribute(rbf_fused_kernel,
                         cudaFuncAttributeMaxDynamicSharedMemorySize, SMEM_TOTAL);
    rbf_fused_kernel<<<ntok / MTILE, NT1, SMEM_TOTAL>>>(x, out_bias, out);
}